// round 12
// baseline (speedup 1.0000x reference)
#include <cuda_runtime.h>

// s_t = mul[x_t, s_{t-1}], s0 = ID (=0). mul is a GROUP table => associative =>
// s_T = (x_{T-1} o ... o x_0) o s0  with  a o b := mul[a*60 + b].
//
// The benchmark's table is structurally cyclic: mul[a,b] = (a+b) % 60 (built
// that way in setup_inputs). Under that table the scan is
//   s_final = (sum_t x_t) % 60.
// Each CTA VERIFIES the cyclic property (all 3600 entries, __syncthreads_and)
// while byte-packing the table for the fully-general fallback, then branches
// uniformly. Fast path: WARP-per-row, no barriers in the hot loop.
//
// R12: R11 measured 73.4MB total LTS bytes in 10.66us = 6.9TB/s = the chip
// LTS cap -> only lever left is fewer bytes. grid 512 -> 256 CTAs halves the
// per-CTA table-verify traffic (7.4MB -> 3.7MB) while keeping perfect
// balance (2048 warps x exactly 4 rows) and sufficient in-flight loads
// (2048 x 16 x 128B = 4.2MB > ~3.4MB BW-latency product).

#define SEQ_T 2048
#define GRP_N 60
#define TBL   (GRP_N * GRP_N)   // 3600

__global__ __launch_bounds__(256)
void a5_scan_kernel(const int* __restrict__ ids,
                    const int* __restrict__ mul,
                    const float* __restrict__ scale,
                    float* __restrict__ out,
                    int B)
{
    __shared__ unsigned char m[TBL];        // 3600 B (fallback path)
    __shared__ int warp_acc[8];             // fallback path
    __shared__ int s_final;                 // fallback path

    const int tid = threadIdx.x;

    // Load table (900 int4 over 256 threads): simultaneously
    //  (a) verify mul[e] == (e/60 + e%60) % 60 for every entry,
    //  (b) byte-pack into smem for the generic fallback.
    bool ok = true;
    for (int i = tid; i < TBL / 4; i += 256) {
        int4 v = reinterpret_cast<const int4*>(mul)[i];
        int e = i * 4;
        int r0 = e / GRP_N,       exp0 = (r0 + (e     - r0 * GRP_N)) % GRP_N;
        int r1 = (e + 1) / GRP_N, exp1 = (r1 + (e + 1 - r1 * GRP_N)) % GRP_N;
        int r2 = (e + 2) / GRP_N, exp2 = (r2 + (e + 2 - r2 * GRP_N)) % GRP_N;
        int r3 = (e + 3) / GRP_N, exp3 = (r3 + (e + 3 - r3 * GRP_N)) % GRP_N;
        ok &= (v.x == exp0) & (v.y == exp1) & (v.z == exp2) & (v.w == exp3);

        uchar4 p;
        p.x = (unsigned char)v.x; p.y = (unsigned char)v.y;
        p.z = (unsigned char)v.z; p.w = (unsigned char)v.w;
        reinterpret_cast<uchar4*>(m)[i] = p;
    }
    const bool cyclic = __syncthreads_and(ok);   // uniform across CTA

    const float sc = *scale;

    if (cyclic) {
        // ---- fast path: warp-per-row, s_final = (sum of ids) % 60 ----
        const int wid = tid >> 5;
        const int lid = tid & 31;
        const int warps_total = gridDim.x * 8;

        for (int row = blockIdx.x * 8 + wid; row < B; row += warps_total) {
            const int4* src = reinterpret_cast<const int4*>(ids + (size_t)row * SEQ_T);

            // 2048 ids = 512 int4; lane l takes int4 (k*32 + l), k = 0..15.
            // Unrolled: independent loads => deep MLP, fully coalesced.
            int s = 0;
            #pragma unroll
            for (int k = 0; k < 16; k++) {
                int4 v = src[k * 32 + lid];
                s += v.x + v.y + v.z + v.w;
            }

            #pragma unroll
            for (int off = 16; off > 0; off >>= 1)
                s += __shfl_down_sync(0xffffffffu, s, off);

            // broadcast total, reduce mod 60 (+ s0 = 0, identity)
            int sf = __shfl_sync(0xffffffffu, s, 0) % GRP_N;

            // 60 floats per row = 30 float2 (row base 240B => 8B aligned)
            if (lid < 30) {
                float2 v2;
                v2.x = ((lid * 2)     == sf ? 10.0f : -10.0f) * sc;
                v2.y = ((lid * 2 + 1) == sf ? 10.0f : -10.0f) * sc;
                reinterpret_cast<float2*>(out + (size_t)row * GRP_N)[lid] = v2;
            }
        }
    } else {
        // ---- generic group-table path (R4, proven correct) ----
        for (int row = blockIdx.x; row < B; row += gridDim.x) {
            const int4* src = reinterpret_cast<const int4*>(ids + (size_t)row * SEQ_T);
            int4 a = src[tid * 2];       // times +0..+3
            int4 b = src[tid * 2 + 1];   // times +4..+7

            int plo = a.x;
            plo = m[a.y * GRP_N + plo];
            plo = m[a.z * GRP_N + plo];
            plo = m[a.w * GRP_N + plo];

            int phi = b.x;
            phi = m[b.y * GRP_N + phi];
            phi = m[b.z * GRP_N + phi];
            phi = m[b.w * GRP_N + phi];

            int p = m[phi * GRP_N + plo];

            #pragma unroll
            for (int off = 1; off < 32; off <<= 1) {
                int q = __shfl_down_sync(0xffffffffu, p, off);
                p = m[q * GRP_N + p];
            }

            if ((tid & 31) == 0) warp_acc[tid >> 5] = p;
            __syncthreads();

            if (tid == 0) {
                int r = warp_acc[0];
                #pragma unroll
                for (int w = 1; w < 8; w++)
                    r = m[warp_acc[w] * GRP_N + r];
                s_final = m[r * GRP_N + 0];          // apply to s0 = id 0
            }
            __syncthreads();

            if (tid < GRP_N)
                out[(size_t)row * GRP_N + tid] =
                    (tid == s_final ? 10.0f : -10.0f) * sc;
        }
    }
}

extern "C" void kernel_launch(void* const* d_in, const int* in_sizes, int n_in,
                              void* d_out, int out_size)
{
    // Identify inputs by element count (robust to metadata ordering):
    //   scale: 1 element, mul: 3600 elements, input_ids: B*T (largest).
    const float* scale = nullptr;
    const int*   ids   = nullptr;
    const int*   mul   = nullptr;
    int ids_elems = 0;

    for (int i = 0; i < n_in; i++) {
        if (in_sizes[i] == 1) {
            scale = (const float*)d_in[i];
        } else if (in_sizes[i] == TBL) {
            mul = (const int*)d_in[i];
        } else {
            ids = (const int*)d_in[i];
            ids_elems = in_sizes[i];
        }
    }

    const int B = ids_elems / SEQ_T;   // 8192

    // 256 CTAs x 8 warps = 2048 warps: every warp covers exactly 4 rows
    // (B = 8192). Minimal table traffic at sufficient memory parallelism.
    int grid = (B + 31) / 32;          // 256 for B=8192
    if (grid > 1184) grid = 1184;
    a5_scan_kernel<<<grid, 256>>>(ids, mul, scale, (float*)d_out, B);
}

// round 13
// speedup vs baseline: 1.0906x; 1.0906x over previous
#include <cuda_runtime.h>

// s_t = mul[x_t, s_{t-1}], s0 = ID (=0). mul is a GROUP table => associative =>
// s_T = (x_{T-1} o ... o x_0) o s0  with  a o b := mul[a*60 + b].
//
// The benchmark's table is structurally cyclic: mul[a,b] = (a+b) % 60 (built
// that way in setup_inputs). Under that table the scan is
//   s_final = (sum_t x_t) % 60.
// Each CTA VERIFIES the cyclic property (all 3600 entries, __syncthreads_and)
// while byte-packing the table for the fully-general fallback, then branches
// uniformly. Fast path: WARP-per-row, no barriers in the hot loop.
//
// R13: grid scan gave 256->11.17, 512->10.66, 1024->11.33us: 512 CTAs
// (2 rows/warp) is the sweet spot -- revert to it. New: PREFETCH the first
// row's first 8 int4 loads into registers BEFORE the table-verify loop, so
// the ~14.4KB table read + verify + barrier overlaps ids bytes already in
// flight instead of dead-starting every CTA.

#define SEQ_T 2048
#define GRP_N 60
#define TBL   (GRP_N * GRP_N)   // 3600

__global__ __launch_bounds__(256)
void a5_scan_kernel(const int* __restrict__ ids,
                    const int* __restrict__ mul,
                    const float* __restrict__ scale,
                    float* __restrict__ out,
                    int B)
{
    __shared__ unsigned char m[TBL];        // 3600 B (fallback path)
    __shared__ int warp_acc[8];             // fallback path
    __shared__ int s_final;                 // fallback path

    const int tid = threadIdx.x;
    const int wid = tid >> 5;
    const int lid = tid & 31;

    // ---- prefetch: first row of this warp, first 8 int4 per lane ----
    // Issued BEFORE the table verify so these global loads are in flight
    // while the table is read/verified. Unconditional w.r.t. the branch.
    const int row0 = blockIdx.x * 8 + wid;
    int4 pre[8];
    if (row0 < B) {
        const int4* src0 = reinterpret_cast<const int4*>(ids + (size_t)row0 * SEQ_T);
        #pragma unroll
        for (int k = 0; k < 8; k++)
            pre[k] = src0[k * 32 + lid];
    }

    // Load table (900 int4 over 256 threads): simultaneously
    //  (a) verify mul[e] == (e/60 + e%60) % 60 for every entry,
    //  (b) byte-pack into smem for the generic fallback.
    bool ok = true;
    for (int i = tid; i < TBL / 4; i += 256) {
        int4 v = reinterpret_cast<const int4*>(mul)[i];
        int e = i * 4;
        int r0 = e / GRP_N,       exp0 = (r0 + (e     - r0 * GRP_N)) % GRP_N;
        int r1 = (e + 1) / GRP_N, exp1 = (r1 + (e + 1 - r1 * GRP_N)) % GRP_N;
        int r2 = (e + 2) / GRP_N, exp2 = (r2 + (e + 2 - r2 * GRP_N)) % GRP_N;
        int r3 = (e + 3) / GRP_N, exp3 = (r3 + (e + 3 - r3 * GRP_N)) % GRP_N;
        ok &= (v.x == exp0) & (v.y == exp1) & (v.z == exp2) & (v.w == exp3);

        uchar4 p;
        p.x = (unsigned char)v.x; p.y = (unsigned char)v.y;
        p.z = (unsigned char)v.z; p.w = (unsigned char)v.w;
        reinterpret_cast<uchar4*>(m)[i] = p;
    }
    const bool cyclic = __syncthreads_and(ok);   // uniform across CTA

    const float sc = *scale;

    if (cyclic) {
        // ---- fast path: warp-per-row, s_final = (sum of ids) % 60 ----
        const int warps_total = gridDim.x * 8;

        // First row: consume prefetched halves + load the rest.
        if (row0 < B) {
            const int4* src0 = reinterpret_cast<const int4*>(ids + (size_t)row0 * SEQ_T);
            int s = 0;
            #pragma unroll
            for (int k = 0; k < 8; k++)
                s += pre[k].x + pre[k].y + pre[k].z + pre[k].w;
            #pragma unroll
            for (int k = 8; k < 16; k++) {
                int4 v = src0[k * 32 + lid];
                s += v.x + v.y + v.z + v.w;
            }

            #pragma unroll
            for (int off = 16; off > 0; off >>= 1)
                s += __shfl_down_sync(0xffffffffu, s, off);

            int sf = __shfl_sync(0xffffffffu, s, 0) % GRP_N;

            if (lid < 30) {
                float2 v2;
                v2.x = ((lid * 2)     == sf ? 10.0f : -10.0f) * sc;
                v2.y = ((lid * 2 + 1) == sf ? 10.0f : -10.0f) * sc;
                reinterpret_cast<float2*>(out + (size_t)row0 * GRP_N)[lid] = v2;
            }
        }

        // Remaining rows (stride loop; for B=8192 each warp does one more).
        for (int row = row0 + warps_total; row < B; row += warps_total) {
            const int4* src = reinterpret_cast<const int4*>(ids + (size_t)row * SEQ_T);

            int s = 0;
            #pragma unroll
            for (int k = 0; k < 16; k++) {
                int4 v = src[k * 32 + lid];
                s += v.x + v.y + v.z + v.w;
            }

            #pragma unroll
            for (int off = 16; off > 0; off >>= 1)
                s += __shfl_down_sync(0xffffffffu, s, off);

            int sf = __shfl_sync(0xffffffffu, s, 0) % GRP_N;

            if (lid < 30) {
                float2 v2;
                v2.x = ((lid * 2)     == sf ? 10.0f : -10.0f) * sc;
                v2.y = ((lid * 2 + 1) == sf ? 10.0f : -10.0f) * sc;
                reinterpret_cast<float2*>(out + (size_t)row * GRP_N)[lid] = v2;
            }
        }
    } else {
        // ---- generic group-table path (R4, proven correct) ----
        for (int row = blockIdx.x; row < B; row += gridDim.x) {
            const int4* src = reinterpret_cast<const int4*>(ids + (size_t)row * SEQ_T);
            int4 a = src[tid * 2];       // times +0..+3
            int4 b = src[tid * 2 + 1];   // times +4..+7

            int plo = a.x;
            plo = m[a.y * GRP_N + plo];
            plo = m[a.z * GRP_N + plo];
            plo = m[a.w * GRP_N + plo];

            int phi = b.x;
            phi = m[b.y * GRP_N + phi];
            phi = m[b.z * GRP_N + phi];
            phi = m[b.w * GRP_N + phi];

            int p = m[phi * GRP_N + plo];

            #pragma unroll
            for (int off = 1; off < 32; off <<= 1) {
                int q = __shfl_down_sync(0xffffffffu, p, off);
                p = m[q * GRP_N + p];
            }

            if ((tid & 31) == 0) warp_acc[tid >> 5] = p;
            __syncthreads();

            if (tid == 0) {
                int r = warp_acc[0];
                #pragma unroll
                for (int w = 1; w < 8; w++)
                    r = m[warp_acc[w] * GRP_N + r];
                s_final = m[r * GRP_N + 0];          // apply to s0 = id 0
            }
            __syncthreads();

            if (tid < GRP_N)
                out[(size_t)row * GRP_N + tid] =
                    (tid == s_final ? 10.0f : -10.0f) * sc;
        }
    }
}

extern "C" void kernel_launch(void* const* d_in, const int* in_sizes, int n_in,
                              void* d_out, int out_size)
{
    // Identify inputs by element count (robust to metadata ordering):
    //   scale: 1 element, mul: 3600 elements, input_ids: B*T (largest).
    const float* scale = nullptr;
    const int*   ids   = nullptr;
    const int*   mul   = nullptr;
    int ids_elems = 0;

    for (int i = 0; i < n_in; i++) {
        if (in_sizes[i] == 1) {
            scale = (const float*)d_in[i];
        } else if (in_sizes[i] == TBL) {
            mul = (const int*)d_in[i];
        } else {
            ids = (const int*)d_in[i];
            ids_elems = in_sizes[i];
        }
    }

    const int B = ids_elems / SEQ_T;   // 8192

    // 512 CTAs x 8 warps = 4096 warps: every warp covers exactly 2 rows
    // (B = 8192). Empirical optimum of the 256/512/1024 grid scan.
    int grid = (B + 15) / 16;          // 512 for B=8192
    if (grid > 1184) grid = 1184;
    a5_scan_kernel<<<grid, 256>>>(ids, mul, scale, (float*)d_out, B);
}